// round 3
// baseline (speedup 1.0000x reference)
#include <cuda_runtime.h>
#include <cstdint>

// CapsNet dynamic routing, factorized (u never materialized), 1 batch per CTA,
// 2 CTAs/SM. W used as bf16 during routing iterations, fp32 for the final pass.

namespace {
constexpr int O_ = 10, U_ = 36, E_ = 16, F_ = 8;
constexpr int N_ = U_ * 32;           // 1152
constexpr int B_ = 256;
constexpr int ITERS_ = 3;
constexpr int T_ = 576;               // 18 warps, 2 CTAs/SM
constexpr int NP = 1156;              // padded c row stride

// shared layout (floats)
constexpr int OFF_XS  = 0;                       // swizzled x  [N][F]   9216
constexpr int OFF_C   = OFF_XS + N_ * F_;        // c [O][NP]           11560
constexpr int OFF_P   = OFF_C + O_ * NP;         // pb [U][164]          5904
constexpr int OFF_SVP = OFF_P + U_ * 164;        // [O][E][4]             640
constexpr int OFF_VV  = OFF_SVP + O_ * E_ * 4;   // [O][E]                160
constexpr int SM_FLOATS = OFF_VV + O_ * E_;      // 27480 -> 109,920 B
} // namespace

__device__ uint32_t wc_g[O_ * U_ * E_ * F_ / 2];  // bf16-packed W (92 KB)

__global__ void conv_w_kernel(const float* __restrict__ Wg) {
    const int i = blockIdx.x * 256 + threadIdx.x;
    if (i < O_ * U_ * E_ * F_ / 2) {
        const uint32_t ua = __float_as_uint(Wg[2 * i]);
        const uint32_t ub = __float_as_uint(Wg[2 * i + 1]);
        const uint32_t ra = (ua + 0x7FFFu + ((ua >> 16) & 1u)) >> 16;
        const uint32_t rb = (ub + 0x7FFFu + ((ub >> 16) & 1u)) >> 16;
        wc_g[i] = ra | (rb << 16);
    }
}

__device__ __forceinline__ float bf_lo(uint32_t v) { return __uint_as_float(v << 16); }
__device__ __forceinline__ float bf_hi(uint32_t v) { return __uint_as_float(v & 0xFFFF0000u); }

__global__ __launch_bounds__(T_, 2)
void caps_route_kernel(const float* __restrict__ x,
                       const float* __restrict__ Wg,
                       float* __restrict__ out) {
    extern __shared__ float sm[];
    float* xs  = sm + OFF_XS;
    float* cc  = sm + OFF_C;
    float* pb  = sm + OFF_P;
    float* svp = sm + OFF_SVP;
    float* vv  = sm + OFF_VV;

    const int tid = threadIdx.x;
    const int b = blockIdx.x;

    const float4* __restrict__ wp4 = reinterpret_cast<const float4*>(Wg);
    const uint4* __restrict__ wc4 = reinterpret_cast<const uint4*>(wc_g);
    float4* xs4 = reinterpret_cast<float4*>(xs);
    float4* pb4 = reinterpret_cast<float4*>(pb);

    // ---- load x tile (coalesced, swizzled store), init c = 1/O ----
    {
        const float4* xg = reinterpret_cast<const float4*>(x) + (size_t)b * (N_ * F_ / 4);
        #pragma unroll
        for (int i = tid; i < N_ * F_ / 4; i += T_) {
            const int q = i ^ ((i >> 3) & 7);
            xs4[q] = xg[i];
        }
    }
    for (int i = tid; i < O_ * NP; i += T_) cc[i] = 0.1f;
    __syncthreads();

    for (int it = 0; it <= ITERS_; ++it) {
        // ---- P2: partial y for (u,fg,oh,sh); 5 o-accumulators ----
        for (int i = tid; i < U_ * 8; i += T_) {
            const int u  = i >> 3;
            const int fg = (i >> 2) & 1;
            const int oh = (i >> 1) & 1;
            const int sh = i & 1;
            const float* cbase = cc + (oh * 5) * NP + u * 32 + sh * 16;
            const int pbase = (u * 32 + sh * 16) * 2 + fg;     // logical float4 idx, s=0
            const int xv4 = sh * 4;
            float4 a0 = make_float4(0.f,0.f,0.f,0.f), a1 = a0, a2 = a0, a3 = a0, a4 = a0;
            #pragma unroll
            for (int j = 0; j < 16; ++j) {
                const int s = (u + j) & 15;
                const int q = (pbase + 2 * s) ^ (xv4 + (s >> 2));
                const float4 xv = xs4[q];
                const float c0 = cbase[0 * NP + s];
                const float c1 = cbase[1 * NP + s];
                const float c2 = cbase[2 * NP + s];
                const float c3 = cbase[3 * NP + s];
                const float c4 = cbase[4 * NP + s];
                a0.x += c0 * xv.x; a0.y += c0 * xv.y; a0.z += c0 * xv.z; a0.w += c0 * xv.w;
                a1.x += c1 * xv.x; a1.y += c1 * xv.y; a1.z += c1 * xv.z; a1.w += c1 * xv.w;
                a2.x += c2 * xv.x; a2.y += c2 * xv.y; a2.z += c2 * xv.z; a2.w += c2 * xv.w;
                a3.x += c3 * xv.x; a3.y += c3 * xv.y; a3.z += c3 * xv.z; a3.w += c3 * xv.w;
                a4.x += c4 * xv.x; a4.y += c4 * xv.y; a4.z += c4 * xv.z; a4.w += c4 * xv.w;
            }
            float4* prow = pb4 + (u * 41 + (fg * 4 + oh * 2 + sh) * 5);
            prow[0] = a0; prow[1] = a1; prow[2] = a2; prow[3] = a3; prow[4] = a4;
        }
        __syncthreads();

        // ---- P3: s[o,e] partials over 4 u-chunks ----
        if (it < ITERS_) {
            // bf16 W
            for (int i = tid; i < O_ * E_ * 4; i += T_) {
                const int o  = i >> 6;
                const int uc = (i >> 4) & 3;
                const int e  = i & 15;
                const int ohh = (o >= 5), ol = o - 5 * ohh;
                float p0 = 0.f;
                #pragma unroll
                for (int jj = 0; jj < 9; ++jj) {
                    const int u = uc * 9 + jj;
                    const uint4 w = wc4[(o * U_ + u) * E_ + e];
                    const int rb = u * 41 + ohh * 2 * 5 + ol;
                    float4 A0 = pb4[rb];            // fg0 sh0
                    const float4 A0b = pb4[rb + 5]; // fg0 sh1
                    float4 A1 = pb4[rb + 20];       // fg1 sh0
                    const float4 A1b = pb4[rb + 25];// fg1 sh1
                    A0.x += A0b.x; A0.y += A0b.y; A0.z += A0b.z; A0.w += A0b.w;
                    A1.x += A1b.x; A1.y += A1b.y; A1.z += A1b.z; A1.w += A1b.w;
                    p0 += bf_lo(w.x) * A0.x + bf_hi(w.x) * A0.y
                        + bf_lo(w.y) * A0.z + bf_hi(w.y) * A0.w
                        + bf_lo(w.z) * A1.x + bf_hi(w.z) * A1.y
                        + bf_lo(w.w) * A1.z + bf_hi(w.w) * A1.w;
                }
                svp[(o * E_ + e) * 4 + uc] = p0;
            }
        } else {
            // fp32 W (final pass feeds the output)
            for (int i = tid; i < O_ * E_ * 4; i += T_) {
                const int o  = i >> 6;
                const int uc = (i >> 4) & 3;
                const int e  = i & 15;
                const int ohh = (o >= 5), ol = o - 5 * ohh;
                float p0 = 0.f;
                #pragma unroll
                for (int jj = 0; jj < 9; ++jj) {
                    const int u = uc * 9 + jj;
                    const int wb = ((o * U_ + u) * E_ + e) * 2;
                    const float4 w0 = wp4[wb + 0];
                    const float4 w1 = wp4[wb + 1];
                    const int rb = u * 41 + ohh * 2 * 5 + ol;
                    float4 A0 = pb4[rb];
                    const float4 A0b = pb4[rb + 5];
                    float4 A1 = pb4[rb + 20];
                    const float4 A1b = pb4[rb + 25];
                    A0.x += A0b.x; A0.y += A0b.y; A0.z += A0b.z; A0.w += A0b.w;
                    A1.x += A1b.x; A1.y += A1b.y; A1.z += A1b.z; A1.w += A1b.w;
                    p0 += w0.x * A0.x + w0.y * A0.y + w0.z * A0.z + w0.w * A0.w
                        + w1.x * A1.x + w1.y * A1.y + w1.z * A1.z + w1.w * A1.w;
                }
                svp[(o * E_ + e) * 4 + uc] = p0;
            }
        }
        __syncthreads();

        // ---- P4: reduce + squash -> vv (160 threads, shuffle over e-groups) ----
        if (tid < O_ * E_) {
            const float* p = svp + tid * 4;
            const float s = (p[0] + p[1]) + (p[2] + p[3]);
            float nsq = s * s;
            #pragma unroll
            for (int m = 1; m <= 8; m <<= 1)
                nsq += __shfl_xor_sync(0xffffffffu, nsq, m);
            const float sc = sqrtf(nsq) / (1.f + nsq);
            vv[tid] = s * sc;
        }
        __syncthreads();

        if (it == ITERS_) break;

        // ---- P5: wv[o,u,fg] into pb (bf16 W) ----
        for (int i = tid; i < O_ * U_ * 2; i += T_) {
            const int fg = i & 1;
            const int ou = i >> 1;
            const int o = ou / U_, u = ou - o * U_;
            const uint32_t* wcb = wc_g + ((o * U_ + u) * E_) * 4 + fg * 2;
            const float* vb = vv + o * E_;
            float4 A = make_float4(0.f,0.f,0.f,0.f);
            #pragma unroll
            for (int e = 0; e < E_; ++e) {
                const uint32_t v0 = wcb[e * 4 + 0];
                const uint32_t v1 = wcb[e * 4 + 1];
                const float ve = vb[e];
                A.x += ve * bf_lo(v0); A.y += ve * bf_hi(v0);
                A.z += ve * bf_lo(v1); A.w += ve * bf_hi(v1);
            }
            pb4[(o * U_ + u) * 2 + fg] = A;
        }
        __syncthreads();

        // ---- P6: c <- normalize_o( c * exp(x . wv) ) ----
        #pragma unroll
        for (int k = 0; k < 2; ++k) {
            const int n = tid + T_ * k;
            const int u = n >> 5;
            const int q0 = (2 * n) ^ ((n >> 2) & 7);
            const float4 x0 = xs4[q0];
            const float4 x1 = xs4[q0 ^ 1];
            float* cp = cc + n;
            const float4* wvb = pb4 + u * 2;
            float t[O_];
            float ss = 0.f;
            #pragma unroll
            for (int o = 0; o < O_; ++o) {
                const float4 w0 = wvb[o * U_ * 2], w1 = wvb[o * U_ * 2 + 1];
                const float d = x0.x * w0.x + x0.y * w0.y + x0.z * w0.z + x0.w * w0.w
                              + x1.x * w1.x + x1.y * w1.y + x1.z * w1.z + x1.w * w1.w;
                const float tv = cp[o * NP] * __expf(d);
                t[o] = tv;
                ss += tv;
            }
            const float inv = 1.0f / ss;
            #pragma unroll
            for (int o = 0; o < O_; ++o) cp[o * NP] = t[o] * inv;
        }
        __syncthreads();
    }

    // ---- write out[b][o][e] ----
    if (tid < O_ * E_) {
        out[(size_t)b * (O_ * E_) + tid] = vv[tid];
    }
}

extern "C" void kernel_launch(void* const* d_in, const int* in_sizes, int n_in,
                              void* d_out, int out_size) {
    (void)in_sizes; (void)n_in; (void)out_size;
    const float* x = (const float*)d_in[0];
    const float* W = (const float*)d_in[1];
    float* out = (float*)d_out;

    conv_w_kernel<<<(O_ * U_ * E_ * F_ / 2 + 255) / 256, 256>>>(W);

    const size_t smem = (size_t)SM_FLOATS * sizeof(float);  // 109,920 B
    cudaFuncSetAttribute(caps_route_kernel,
                         cudaFuncAttributeMaxDynamicSharedMemorySize, (int)smem);
    caps_route_kernel<<<B_, T_, smem>>>(x, W, out);
}

// round 4
// speedup vs baseline: 1.3165x; 1.3165x over previous
#include <cuda_runtime.h>

// CapsNet dynamic routing, factorized (u never materialized), BT=2 batches/CTA:
//   y[o,u,f]  = sum_s c[o,n] x[n,f]
//   s[o,e]    = sum_{u,f} W[o,u,e,f] y[o,u,f]   ; v = squash(s)
//   wv[o,u,f] = sum_e W[o,u,e,f] v[o,e]
//   c[o,n]   <- normalize_o( c[o,n] * exp(sum_f x[n,f] wv[o,u,f]) )

namespace {
constexpr int O_ = 10, U_ = 36, E_ = 16, F_ = 8;
constexpr int N_ = 1152;
constexpr int B_ = 256;
constexpr int BT = 2;
constexpr int T_ = 1024;             // 32 warps, 1 CTA/SM
constexpr int NP = 1157;             // padded c row stride (conflict-free pattern)

// shared layout (floats)
constexpr int OFF_XS  = 0;                        // swizzled x [BT][N][F]  18432
constexpr int OFF_C   = OFF_XS + BT * N_ * F_;    // c [BT][O][NP]          23140
constexpr int OFF_P   = OFF_C + BT * O_ * NP;     // pb 2880 float4         11520
constexpr int OFF_SVP = OFF_P + 11520;            // [BT][O][E][4]           1280
constexpr int OFF_VV  = OFF_SVP + BT * O_ * E_ * 4; // [BT][O][E]             320
constexpr int SM_FLOATS = OFF_VV + BT * O_ * E_;  // 54692 -> 218768 B
} // namespace

__global__ __launch_bounds__(T_, 1)
void caps_route_kernel(const float* __restrict__ x,
                       const float* __restrict__ Wg,
                       float* __restrict__ out) {
    extern __shared__ float sm[];
    float* xs  = sm + OFF_XS;
    float* cc  = sm + OFF_C;
    float* pb  = sm + OFF_P;
    float* svp = sm + OFF_SVP;
    float* vv  = sm + OFF_VV;

    const int tid = threadIdx.x;
    const int b0 = blockIdx.x * BT;

    const float4* __restrict__ wp4 = reinterpret_cast<const float4*>(Wg);
    float4* xs4 = reinterpret_cast<float4*>(xs);
    float4* pb4 = reinterpret_cast<float4*>(pb);

    // ---- load x tiles (coalesced gmem read, swizzled smem store); c = 1/O ----
    {
        const float4* xg = reinterpret_cast<const float4*>(x) + (size_t)b0 * (N_ * F_ / 4);
        #pragma unroll
        for (int i = tid; i < BT * N_ * F_ / 4; i += T_) {
            xs4[i ^ ((i >> 3) & 7)] = xg[i];
        }
    }
    for (int i = tid; i < BT * O_ * NP; i += T_) cc[i] = 0.1f;
    __syncthreads();

    // P2 task decode (576 tasks, one per thread tid<576)
    const int p2_sh = tid & 1;
    const int p2_bb = (tid >> 1) & 1;
    const int p2_fg = (tid >> 2) & 1;
    const int p2_oh = (tid >> 3) & 1;
    const int p2_u  = tid >> 4;
    const float* p2_cb = cc + (p2_bb * 10 + p2_oh * 5) * NP + p2_u * 32 + p2_sh * 16;
    const int p2_pbase = (p2_bb * N_ + p2_u * 32 + p2_sh * 16) * 2 + p2_fg;

    for (int it = 0; it < 4; ++it) {
        // ---- P2: y partials for (bb,u,fg,oh,sh); 5 o-accumulators ----
        if (tid < 576) {
            float4 a0 = make_float4(0.f,0.f,0.f,0.f), a1 = a0, a2 = a0, a3 = a0, a4 = a0;
            #pragma unroll
            for (int j = 0; j < 16; ++j) {
                const int s = (p2_u + j) & 15;          // rotation: bank decollide
                const int p = p2_pbase + 2 * s;
                const float4 xv = xs4[p ^ ((p >> 3) & 7)];
                const float c0 = p2_cb[s];
                const float c1 = p2_cb[NP + s];
                const float c2 = p2_cb[2 * NP + s];
                const float c3 = p2_cb[3 * NP + s];
                const float c4 = p2_cb[4 * NP + s];
                a0.x += c0 * xv.x; a0.y += c0 * xv.y; a0.z += c0 * xv.z; a0.w += c0 * xv.w;
                a1.x += c1 * xv.x; a1.y += c1 * xv.y; a1.z += c1 * xv.z; a1.w += c1 * xv.w;
                a2.x += c2 * xv.x; a2.y += c2 * xv.y; a2.z += c2 * xv.z; a2.w += c2 * xv.w;
                a3.x += c3 * xv.x; a3.y += c3 * xv.y; a3.z += c3 * xv.z; a3.w += c3 * xv.w;
                a4.x += c4 * xv.x; a4.y += c4 * xv.y; a4.z += c4 * xv.z; a4.w += c4 * xv.w;
            }
            float4* pr = pb4 + tid * 5;
            pr[0] = a0; pr[1] = a1; pr[2] = a2; pr[3] = a3; pr[4] = a4;
        }
        __syncthreads();

        // ---- P3: s[bb,o,e] partials over 4 u-chunks.
        // e in low 4 lane bits: y reads are 16-lane broadcasts, W coalesced. ----
        for (int i = tid; i < 1280; i += T_) {
            const int e  = i & 15;
            const int uc = (i >> 4) & 3;
            const int r  = i >> 6;                     // 0..19
            const int bb = (r >= 10);
            const int o  = r - 10 * bb;
            const int oh = (o >= 5);
            const int k  = o - 5 * oh;
            float p = 0.f;
            #pragma unroll
            for (int jj = 0; jj < 9; ++jj) {
                const int u = uc * 9 + jj;
                const int pbase = (u << 4) | (oh << 3) | (p2_bb * 0) | (bb << 1);
                float4 A0 = pb4[(pbase | 0) * 5 + k];       // fg0 sh0
                const float4 t0 = pb4[(pbase | 1) * 5 + k]; // fg0 sh1
                float4 A1 = pb4[(pbase | 4) * 5 + k];       // fg1 sh0
                const float4 t1 = pb4[(pbase | 5) * 5 + k]; // fg1 sh1
                A0.x += t0.x; A0.y += t0.y; A0.z += t0.z; A0.w += t0.w;
                A1.x += t1.x; A1.y += t1.y; A1.z += t1.z; A1.w += t1.w;
                const int wb = ((o * U_ + u) * E_ + e) * 2;
                const float4 w0 = wp4[wb];
                const float4 w1 = wp4[wb + 1];
                p += w0.x * A0.x + w0.y * A0.y + w0.z * A0.z + w0.w * A0.w
                   + w1.x * A1.x + w1.y * A1.y + w1.z * A1.z + w1.w * A1.w;
            }
            svp[((bb * 10 + o) * 16 + e) * 4 + uc] = p;
        }
        __syncthreads();

        // ---- P4: reduce partials + squash -> vv (320 threads = 10 full warps) ----
        if (tid < 320) {
            const float* pp = svp + tid * 4;
            const float s = (pp[0] + pp[1]) + (pp[2] + pp[3]);
            float nsq = s * s;
            #pragma unroll
            for (int m = 1; m <= 8; m <<= 1)
                nsq += __shfl_xor_sync(0xffffffffu, nsq, m);
            vv[tid] = s * (sqrtf(nsq) / (1.f + nsq));
        }
        __syncthreads();

        if (it == 3) break;

        // ---- P5: wv[bb,o,u,fg] into pb (aliased); one W read serves both bb ----
        if (tid < 720) {
            const int fg = tid & 1;
            const int ou = tid >> 1;
            const int o = ou / U_, u = ou - o * U_;
            const float4* wp = wp4 + ((o * U_ + u) * E_) * 2 + fg;
            const float* v0 = vv + o * 16;
            const float* v1 = v0 + 160;
            float4 A = make_float4(0.f,0.f,0.f,0.f);
            float4 Bv = A;
            #pragma unroll
            for (int e = 0; e < E_; ++e) {
                const float4 w = wp[e * 2];
                const float ve0 = v0[e], ve1 = v1[e];
                A.x  += ve0 * w.x; A.y  += ve0 * w.y; A.z  += ve0 * w.z; A.w  += ve0 * w.w;
                Bv.x += ve1 * w.x; Bv.y += ve1 * w.y; Bv.z += ve1 * w.z; Bv.w += ve1 * w.w;
            }
            pb4[(o * U_ + u) * 2 + fg] = A;
            pb4[720 + (o * U_ + u) * 2 + fg] = Bv;
        }
        __syncthreads();

        // ---- P6: c <- normalize_o( c * exp(x . wv) ) ----
        #pragma unroll
        for (int kk = 0; kk < 3; ++kk) {
            const int idx = tid + T_ * kk;
            if (idx < BT * N_) {
                const int bb = (idx >= N_);
                const int n = idx - bb * N_;
                const int u = n >> 5;
                const int p = (bb * N_ + n) * 2;
                const int q = p ^ ((p >> 3) & 7);
                const float4 x0 = xs4[q];
                const float4 x1 = xs4[q ^ 1];
                const float4* wvb = pb4 + bb * 720 + u * 2;
                float* cp = cc + (bb * 10) * NP + n;
                float t[O_];
                float ss = 0.f;
                #pragma unroll
                for (int o = 0; o < O_; ++o) {
                    const float4 w0 = wvb[o * 72], w1 = wvb[o * 72 + 1];
                    const float d = x0.x * w0.x + x0.y * w0.y + x0.z * w0.z + x0.w * w0.w
                                  + x1.x * w1.x + x1.y * w1.y + x1.z * w1.z + x1.w * w1.w;
                    const float tv = cp[o * NP] * __expf(d);
                    t[o] = tv;
                    ss += tv;
                }
                const float inv = 1.0f / ss;
                #pragma unroll
                for (int o = 0; o < O_; ++o) cp[o * NP] = t[o] * inv;
            }
        }
        __syncthreads();
    }

    // ---- write out[b][o][e] ----
    if (tid < BT * O_ * E_) {
        const int bb = tid / (O_ * E_);
        out[(size_t)(b0 + bb) * (O_ * E_) + (tid - bb * O_ * E_)] = vv[tid];
    }
}

extern "C" void kernel_launch(void* const* d_in, const int* in_sizes, int n_in,
                              void* d_out, int out_size) {
    (void)in_sizes; (void)n_in; (void)out_size;
    const float* x = (const float*)d_in[0];
    const float* W = (const float*)d_in[1];
    float* out = (float*)d_out;

    const size_t smem = (size_t)SM_FLOATS * sizeof(float);  // 218,768 B
    cudaFuncSetAttribute(caps_route_kernel,
                         cudaFuncAttributeMaxDynamicSharedMemorySize, (int)smem);
    caps_route_kernel<<<B_ / BT, T_, smem>>>(x, W, out);
}

// round 5
// speedup vs baseline: 1.3693x; 1.0401x over previous
#include <cuda_runtime.h>

// CapsNet dynamic routing, factorized (u never materialized), BT=2 batches/CTA:
//   y[o,u,f]  = sum_s c[o,n] x[n,f]
//   s[o,e]    = sum_{u,f} W[o,u,e,f] y[o,u,f]   ; v = squash(s)   (P3, fused squash)
//   wv[o,u,f] = sum_e W[o,u,e,f] v[o,e]                            (P5)
//   c[o,n]   <- normalize_o( c[o,n] * exp(sum_f x[n,f] wv[o,u,f]) ) (P6)

namespace {
constexpr int O_ = 10, U_ = 36, E_ = 16, F_ = 8;
constexpr int N_ = 1152;
constexpr int B_ = 256;
constexpr int BT = 2;
constexpr int T_ = 1024;             // 32 warps, 1 CTA/SM
constexpr int NP = 1157;             // padded c row stride

// shared layout (floats)
constexpr int OFF_XS = 0;                        // swizzled x [BT][N][F]  18432
constexpr int OFF_C  = OFF_XS + BT * N_ * F_;    // c [BT][O][NP]          23140
constexpr int OFF_P  = OFF_C + BT * O_ * NP;     // pb 2880 float4         11520
constexpr int OFF_VV = OFF_P + 11520;            // [BT][O][E]               320
constexpr int SM_FLOATS = OFF_VV + BT * O_ * E_; // 53412 -> 213,648 B
} // namespace

__global__ __launch_bounds__(T_, 1)
void caps_route_kernel(const float* __restrict__ x,
                       const float* __restrict__ Wg,
                       float* __restrict__ out) {
    extern __shared__ float sm[];
    float* xs = sm + OFF_XS;
    float* cc = sm + OFF_C;
    float* pb = sm + OFF_P;
    float* vv = sm + OFF_VV;

    const int tid = threadIdx.x;
    const int b0 = blockIdx.x * BT;

    const float4* __restrict__ wp4 = reinterpret_cast<const float4*>(Wg);
    float4* xs4 = reinterpret_cast<float4*>(xs);
    float4* pb4 = reinterpret_cast<float4*>(pb);

    // ---- load x tiles (coalesced gmem read, swizzled smem store); c = 1/O ----
    {
        const float4* xg = reinterpret_cast<const float4*>(x) + (size_t)b0 * (N_ * F_ / 4);
        #pragma unroll
        for (int i = tid; i < BT * N_ * F_ / 4; i += T_) {
            xs4[i ^ ((i >> 3) & 7)] = xg[i];
        }
    }
    for (int i = tid; i < BT * O_ * NP; i += T_) cc[i] = 0.1f;
    __syncthreads();

    // P2 task decode (576 tasks, one per thread tid<576)
    const int p2_sh = tid & 1;
    const int p2_bb = (tid >> 1) & 1;
    const int p2_fg = (tid >> 2) & 1;
    const int p2_oh = (tid >> 3) & 1;
    const int p2_u  = tid >> 4;
    const float* p2_cb = cc + (p2_bb * 10 + p2_oh * 5) * NP + p2_u * 32 + p2_sh * 16;
    const int p2_pbase = (p2_bb * N_ + p2_u * 32 + p2_sh * 16) * 2 + p2_fg;

    // P3 decode: warp owns (bb,o); lanes = (e low 4 bits, ch bit 4)
    const int warp = tid >> 5;
    const int lane = tid & 31;
    const int p3_e  = lane & 15;
    const int p3_ch = lane >> 4;
    const int p3_bb = (warp >= 10);
    const int p3_o  = warp - 10 * p3_bb;
    const int p3_oh = (p3_o >= 5);
    const int p3_k  = p3_o - 5 * p3_oh;

    for (int it = 0; it < 4; ++it) {
        // ---- P2: y partials for (bb,u,fg,oh,sh); 5 o-accumulators ----
        if (tid < 576) {
            float4 a0 = make_float4(0.f,0.f,0.f,0.f), a1 = a0, a2 = a0, a3 = a0, a4 = a0;
            #pragma unroll
            for (int j = 0; j < 16; ++j) {
                const int s = (p2_u + j) & 15;          // rotation: bank decollide
                const int p = p2_pbase + 2 * s;
                const float4 xv = xs4[p ^ ((p >> 3) & 7)];
                const float c0 = p2_cb[s];
                const float c1 = p2_cb[NP + s];
                const float c2 = p2_cb[2 * NP + s];
                const float c3 = p2_cb[3 * NP + s];
                const float c4 = p2_cb[4 * NP + s];
                a0.x += c0 * xv.x; a0.y += c0 * xv.y; a0.z += c0 * xv.z; a0.w += c0 * xv.w;
                a1.x += c1 * xv.x; a1.y += c1 * xv.y; a1.z += c1 * xv.z; a1.w += c1 * xv.w;
                a2.x += c2 * xv.x; a2.y += c2 * xv.y; a2.z += c2 * xv.z; a2.w += c2 * xv.w;
                a3.x += c3 * xv.x; a3.y += c3 * xv.y; a3.z += c3 * xv.z; a3.w += c3 * xv.w;
                a4.x += c4 * xv.x; a4.y += c4 * xv.y; a4.z += c4 * xv.z; a4.w += c4 * xv.w;
            }
            float4* pr = pb4 + tid * 5;
            pr[0] = a0; pr[1] = a1; pr[2] = a2; pr[3] = a3; pr[4] = a4;
        }
        __syncthreads();

        // ---- P3 (+squash fused): warp (bb,o); lane (e,ch of 18 u) -> vv ----
        if (warp < 20) {
            float p = 0.f;
            #pragma unroll 6
            for (int jj = 0; jj < 18; ++jj) {
                const int u = p3_ch * 18 + jj;
                const int pbase = (u << 4) | (p3_oh << 3) | (p3_bb << 1);
                float4 A0 = pb4[(pbase | 0) * 5 + p3_k];       // fg0 sh0
                const float4 t0 = pb4[(pbase | 1) * 5 + p3_k]; // fg0 sh1
                float4 A1 = pb4[(pbase | 4) * 5 + p3_k];       // fg1 sh0
                const float4 t1 = pb4[(pbase | 5) * 5 + p3_k]; // fg1 sh1
                A0.x += t0.x; A0.y += t0.y; A0.z += t0.z; A0.w += t0.w;
                A1.x += t1.x; A1.y += t1.y; A1.z += t1.z; A1.w += t1.w;
                const int wb = ((p3_o * U_ + u) * E_ + p3_e) * 2;
                const float4 w0 = wp4[wb];
                const float4 w1 = wp4[wb + 1];
                p += w0.x * A0.x + w0.y * A0.y + w0.z * A0.z + w0.w * A0.w
                   + w1.x * A1.x + w1.y * A1.y + w1.z * A1.z + w1.w * A1.w;
            }
            // merge ch halves -> every lane holds s[bb,o,e]
            const float s = p + __shfl_xor_sync(0xffffffffu, p, 16);
            float nsq = s * s;
            #pragma unroll
            for (int m = 1; m <= 8; m <<= 1)
                nsq += __shfl_xor_sync(0xffffffffu, nsq, m);
            const float sc = sqrtf(nsq) / (1.f + nsq);
            if (p3_ch == 0)
                vv[(p3_bb * 10 + p3_o) * 16 + p3_e] = s * sc;
        }
        __syncthreads();

        if (it == 3) break;

        // ---- P5: wv[bb,o,u,fg] into pb (aliased); one W read serves both bb ----
        if (tid < 720) {
            const int fg = tid & 1;
            const int ou = tid >> 1;
            const int o = ou / U_, u = ou - o * U_;
            const float4* wp = wp4 + ((o * U_ + u) * E_) * 2 + fg;
            const float* v0 = vv + o * 16;
            const float* v1 = v0 + 160;
            float4 A = make_float4(0.f,0.f,0.f,0.f);
            float4 Bv = A;
            #pragma unroll
            for (int e = 0; e < E_; ++e) {
                const float4 w = wp[e * 2];
                const float ve0 = v0[e], ve1 = v1[e];
                A.x  += ve0 * w.x; A.y  += ve0 * w.y; A.z  += ve0 * w.z; A.w  += ve0 * w.w;
                Bv.x += ve1 * w.x; Bv.y += ve1 * w.y; Bv.z += ve1 * w.z; Bv.w += ve1 * w.w;
            }
            pb4[(o * U_ + u) * 2 + fg] = A;
            pb4[720 + (o * U_ + u) * 2 + fg] = Bv;
        }
        __syncthreads();

        // ---- P6: c <- normalize_o( c * exp(x . wv) ) ----
        #pragma unroll
        for (int kk = 0; kk < 3; ++kk) {
            const int idx = tid + T_ * kk;
            if (idx < BT * N_) {
                const int bb = (idx >= N_);
                const int n = idx - bb * N_;
                const int u = n >> 5;
                const int p = (bb * N_ + n) * 2;
                const int q = p ^ ((p >> 3) & 7);
                const float4 x0 = xs4[q];
                const float4 x1 = xs4[q ^ 1];
                const float4* wvb = pb4 + bb * 720 + u * 2;
                float* cp = cc + (bb * 10) * NP + n;
                float t[O_];
                float ss = 0.f;
                #pragma unroll
                for (int o = 0; o < O_; ++o) {
                    const float4 w0 = wvb[o * 72], w1 = wvb[o * 72 + 1];
                    const float d = x0.x * w0.x + x0.y * w0.y + x0.z * w0.z + x0.w * w0.w
                                  + x1.x * w1.x + x1.y * w1.y + x1.z * w1.z + x1.w * w1.w;
                    const float tv = cp[o * NP] * __expf(d);
                    t[o] = tv;
                    ss += tv;
                }
                const float inv = 1.0f / ss;
                #pragma unroll
                for (int o = 0; o < O_; ++o) cp[o * NP] = t[o] * inv;
            }
        }
        __syncthreads();
    }

    // ---- write out[b][o][e] ----
    if (tid < BT * O_ * E_) {
        const int bb = tid / (O_ * E_);
        out[(size_t)(b0 + bb) * (O_ * E_) + (tid - bb * O_ * E_)] = vv[tid];
    }
}

extern "C" void kernel_launch(void* const* d_in, const int* in_sizes, int n_in,
                              void* d_out, int out_size) {
    (void)in_sizes; (void)n_in; (void)out_size;
    const float* x = (const float*)d_in[0];
    const float* W = (const float*)d_in[1];
    float* out = (float*)d_out;

    const size_t smem = (size_t)SM_FLOATS * sizeof(float);  // 213,648 B
    cudaFuncSetAttribute(caps_route_kernel,
                         cudaFuncAttributeMaxDynamicSharedMemorySize, (int)smem);
    caps_route_kernel<<<B_ / BT, T_, smem>>>(x, W, out);
}